// round 4
// baseline (speedup 1.0000x reference)
#include <cuda_runtime.h>

// Shapes (fixed by the problem)
constexpr int BB = 64;    // batch
constexpr int KK = 256;   // feature dim K
constexpr int TT = 64;    // word tokens
constexpr int DFE = 768;  // image channels
constexpr int NN = 1024;  // regions

// Scratch (device globals: allocation-free contract)
__device__ float g_v[BB * KK * NN];   // v  [B,K,N]  64 MB
__device__ float g_s[BB * TT * NN];   // s / alpha (in place) 16 MB
__device__ float g_c[BB * KK * TT];   // c  [B,K,T]  4 MB

typedef unsigned long long u64;

// ---- packed f32x2 helpers (Blackwell FFMA2) -------------------------------
__device__ __forceinline__ u64 bcast2(float x) {
    u64 r;
    asm("mov.b64 %0, {%1, %1};" : "=l"(r) : "f"(x));
    return r;
}
__device__ __forceinline__ void fma2(u64& c, u64 a, u64 b) {
    asm("fma.rn.f32x2 %0, %1, %2, %3;" : "=l"(c) : "l"(a), "l"(b), "l"(c));
}
__device__ __forceinline__ float2 u2f2(u64 v) {
    float2 f;
    asm("mov.b64 {%0, %1}, %2;" : "=f"(f.x), "=f"(f.y) : "l"(v));
    return f;
}

// ---------------------------------------------------------------------------
// TN GEMM: C[m][n] = sum_k A[k*lda + m] * B[k*ldb + n]  (+ bias[m])
// Tile TM x TN, 256 threads (16x16), each thread RM x RN (RN must be 4).
// Inner product uses packed f32x2 FMAs (rows paired).
// ---------------------------------------------------------------------------
template <int TM, int TN_, int RM, int RN, bool BIAS>
__global__ __launch_bounds__(256) void gemm_tn(
    const float* __restrict__ A, const float* __restrict__ B,
    const float* __restrict__ bias, float* __restrict__ C,
    int Ktot, int lda, int ldb, int ldc, long aB, long bB, long cB)
{
    static_assert(RN == 4 && (RM % 4) == 0, "layout");
    constexpr int KC = 16;
    __shared__ float As[KC][TM];
    __shared__ float Bs[KC][TN_];

    const int b  = blockIdx.z;
    const int m0 = blockIdx.y * TM;
    const int n0 = blockIdx.x * TN_;
    const float* Ab = A + (long)b * aB;
    const float* Bb = B + (long)b * bB;
    float* Cb = C + (long)b * cB;

    const int tid = threadIdx.x;
    const int tx = tid & 15, ty = tid >> 4;

    u64 acc[RM / 2][RN];
#pragma unroll
    for (int p = 0; p < RM / 2; p++)
#pragma unroll
        for (int j = 0; j < RN; j++) acc[p][j] = 0ull;

    constexpr int A4 = KC * TM / 4;    // float4 slots in A tile
    constexpr int B4 = KC * TN_ / 4;

    for (int k0 = 0; k0 < Ktot; k0 += KC) {
#pragma unroll
        for (int l = 0; l < A4 / 256; l++) {
            int idx = tid + l * 256;
            int r = idx / (TM / 4), c = idx % (TM / 4);
            *(float4*)&As[r][c * 4] =
                *(const float4*)&Ab[(long)(k0 + r) * lda + m0 + c * 4];
        }
#pragma unroll
        for (int l = 0; l < B4 / 256; l++) {
            int idx = tid + l * 256;
            int r = idx / (TN_ / 4), c = idx % (TN_ / 4);
            *(float4*)&Bs[r][c * 4] =
                *(const float4*)&Bb[(long)(k0 + r) * ldb + n0 + c * 4];
        }
        __syncthreads();

#pragma unroll
        for (int kk = 0; kk < KC; kk++) {
            u64 a2[RM / 2];
#pragma unroll
            for (int q = 0; q < RM / 4; q++) {
                ulonglong2 t = *(const ulonglong2*)&As[kk][ty * RM + q * 4];
                a2[2 * q]     = t.x;
                a2[2 * q + 1] = t.y;
            }
            float4 bvf = *(const float4*)&Bs[kk][tx * RN];
            u64 b2[4] = {bcast2(bvf.x), bcast2(bvf.y), bcast2(bvf.z), bcast2(bvf.w)};
#pragma unroll
            for (int p = 0; p < RM / 2; p++)
#pragma unroll
                for (int j = 0; j < RN; j++) fma2(acc[p][j], a2[p], b2[j]);
        }
        __syncthreads();
    }

#pragma unroll
    for (int p = 0; p < RM / 2; p++) {
        int r0 = m0 + ty * RM + 2 * p;
        float bi0 = 0.f, bi1 = 0.f;
        if (BIAS) { bi0 = bias[r0]; bi1 = bias[r0 + 1]; }
        float2 f0 = u2f2(acc[p][0]);
        float2 f1 = u2f2(acc[p][1]);
        float2 f2 = u2f2(acc[p][2]);
        float2 f3 = u2f2(acc[p][3]);
        float4 o0 = make_float4(f0.x + bi0, f1.x + bi0, f2.x + bi0, f3.x + bi0);
        float4 o1 = make_float4(f0.y + bi1, f1.y + bi1, f2.y + bi1, f3.y + bi1);
        *(float4*)&Cb[(long)r0 * ldc + n0 + tx * RN]       = o0;
        *(float4*)&Cb[(long)(r0 + 1) * ldc + n0 + tx * RN] = o1;
    }
}

// ---------------------------------------------------------------------------
// Row softmax over N=1024 with gamma scaling (in place).  1 block per row.
// ---------------------------------------------------------------------------
__global__ __launch_bounds__(256) void softmax_k(float* __restrict__ S,
                                                 const float* __restrict__ gp)
{
    __shared__ float red[8];
    const long row = blockIdx.x;
    float* s = S + row * NN;
    const int tid = threadIdx.x;
    const float g = *gp;

    float4 v = *(const float4*)&s[tid * 4];
    v.x *= g; v.y *= g; v.z *= g; v.w *= g;

    float m = fmaxf(fmaxf(v.x, v.y), fmaxf(v.z, v.w));
#pragma unroll
    for (int o = 16; o > 0; o >>= 1) m = fmaxf(m, __shfl_xor_sync(0xffffffffu, m, o));
    if ((tid & 31) == 0) red[tid >> 5] = m;
    __syncthreads();
    m = red[0];
#pragma unroll
    for (int i = 1; i < 8; i++) m = fmaxf(m, red[i]);
    __syncthreads();

    float e0 = __expf(v.x - m), e1 = __expf(v.y - m);
    float e2 = __expf(v.z - m), e3 = __expf(v.w - m);
    float sum = (e0 + e1) + (e2 + e3);
#pragma unroll
    for (int o = 16; o > 0; o >>= 1) sum += __shfl_xor_sync(0xffffffffu, sum, o);
    if ((tid & 31) == 0) red[tid >> 5] = sum;
    __syncthreads();
    sum = ((red[0] + red[1]) + (red[2] + red[3])) +
          ((red[4] + red[5]) + (red[6] + red[7]));
    float r = 1.0f / sum;
    float4 o = make_float4(e0 * r, e1 * r, e2 * r, e3 * r);
    *(float4*)&s[tid * 4] = o;
}

// ---------------------------------------------------------------------------
// NT GEMM: c[b][m][t] = sum_n v[b][m][n] * alpha[b][t][n]
// 64(m) x 64(t) tile per block, n in chunks of 16 via smem (padded rows).
// ---------------------------------------------------------------------------
__global__ __launch_bounds__(256) void gemm_nt_c(const float* __restrict__ V,
                                                 const float* __restrict__ Al,
                                                 float* __restrict__ C)
{
    __shared__ float Vs[64][17];
    __shared__ float As[64][17];
    const int b  = blockIdx.z;
    const int m0 = blockIdx.y * 64;
    const float* Vb = V + (long)b * KK * NN + (long)m0 * NN;
    const float* Ab = Al + (long)b * TT * NN;
    const int tid = threadIdx.x;
    const int tx = tid & 15, ty = tid >> 4;
    const int lr = tid >> 2, lc = (tid & 3) * 4;

    float acc[4][4] = {};
    for (int n0 = 0; n0 < NN; n0 += 16) {
        float4 v4 = *(const float4*)&Vb[(long)lr * NN + n0 + lc];
        float4 a4 = *(const float4*)&Ab[(long)lr * NN + n0 + lc];
        Vs[lr][lc] = v4.x; Vs[lr][lc + 1] = v4.y; Vs[lr][lc + 2] = v4.z; Vs[lr][lc + 3] = v4.w;
        As[lr][lc] = a4.x; As[lr][lc + 1] = a4.y; As[lr][lc + 2] = a4.z; As[lr][lc + 3] = a4.w;
        __syncthreads();
#pragma unroll
        for (int nn = 0; nn < 16; nn++) {
            float av[4], bv[4];
#pragma unroll
            for (int i = 0; i < 4; i++) av[i] = Vs[ty * 4 + i][nn];
#pragma unroll
            for (int j = 0; j < 4; j++) bv[j] = As[tx * 4 + j][nn];
#pragma unroll
            for (int i = 0; i < 4; i++)
#pragma unroll
                for (int j = 0; j < 4; j++) acc[i][j] = fmaf(av[i], bv[j], acc[i][j]);
        }
        __syncthreads();
    }
    float* Cb = C + (long)b * KK * TT + (long)m0 * TT;
#pragma unroll
    for (int i = 0; i < 4; i++) {
        float4 o = make_float4(acc[i][0], acc[i][1], acc[i][2], acc[i][3]);
        *(float4*)&Cb[(ty * 4 + i) * TT + tx * 4] = o;
    }
}

// ---------------------------------------------------------------------------
// Finalize: norms + cos[b][i][j] = (sum_k c[k][i] e[k][j]) / (lc[i] le[j])
// One block per batch.
// ---------------------------------------------------------------------------
__global__ __launch_bounds__(256) void finalize_k(const float* __restrict__ Cm,
                                                  const float* __restrict__ E,
                                                  float* __restrict__ Out)
{
    __shared__ float rn[128];          // [0:64) = 1/lc, [64:128) = 1/le
    __shared__ float As[16][64];
    __shared__ float Bs[16][64];
    const int b = blockIdx.x;
    const float* cb = Cm + (long)b * KK * TT;
    const float* eb = E + (long)b * KK * TT;
    const int tid = threadIdx.x;

    if (tid < 128) {
        const float* p = (tid < 64) ? cb : eb;
        int t = tid & 63;
        float ss = 0.f;
        for (int k = 0; k < KK; k++) {
            float x = p[k * TT + t];
            ss = fmaf(x, x, ss);
        }
        rn[tid] = rsqrtf(ss);
    }

    const int tx = tid & 15, ty = tid >> 4;
    float acc[4][4] = {};
    for (int k0 = 0; k0 < KK; k0 += 16) {
        *(float4*)&As[ty][tx * 4] = *(const float4*)&cb[(k0 + ty) * TT + tx * 4];
        *(float4*)&Bs[ty][tx * 4] = *(const float4*)&eb[(k0 + ty) * TT + tx * 4];
        __syncthreads();
#pragma unroll
        for (int kk = 0; kk < 16; kk++) {
            float4 a4 = *(const float4*)&As[kk][ty * 4];
            float4 b4 = *(const float4*)&Bs[kk][tx * 4];
            float av[4] = {a4.x, a4.y, a4.z, a4.w};
            float bv[4] = {b4.x, b4.y, b4.z, b4.w};
#pragma unroll
            for (int i = 0; i < 4; i++)
#pragma unroll
                for (int j = 0; j < 4; j++) acc[i][j] = fmaf(av[i], bv[j], acc[i][j]);
        }
        __syncthreads();
    }

    float* ob = Out + (long)b * TT * TT;
#pragma unroll
    for (int i = 0; i < 4; i++) {
        int ii = ty * 4 + i;
        float ri = rn[ii];
        float4 o;
        o.x = acc[i][0] * ri * rn[64 + tx * 4 + 0];
        o.y = acc[i][1] * ri * rn[64 + tx * 4 + 1];
        o.z = acc[i][2] * ri * rn[64 + tx * 4 + 2];
        o.w = acc[i][3] * ri * rn[64 + tx * 4 + 3];
        *(float4*)&ob[ii * TT + tx * 4] = o;
    }
}

// ---------------------------------------------------------------------------
extern "C" void kernel_launch(void* const* d_in, const int* in_sizes, int n_in,
                              void* d_out, int out_size)
{
    const float* e  = (const float*)d_in[0];   // [B,K,T]
    const float* f  = (const float*)d_in[1];   // [B,DF,N]
    const float* gp = (const float*)d_in[2];   // scalar gamma
    const float* W  = (const float*)d_in[3];   // [DF,K]
    const float* bs = (const float*)d_in[4];   // [K]
    float* out = (float*)d_out;                // [B,T,T]

    float *pv = nullptr, *ps = nullptr, *pc = nullptr;
    cudaGetSymbolAddress((void**)&pv, g_v);
    cudaGetSymbolAddress((void**)&ps, g_s);
    cudaGetSymbolAddress((void**)&pc, g_c);

    // 1) v = W^T f + b : per batch K x N, reduce DF
    gemm_tn<128, 64, 8, 4, true><<<dim3(NN / 64, KK / 128, BB), 256>>>(
        W, f, bs, pv, DFE, KK, NN, NN, 0L, (long)DFE * NN, (long)KK * NN);

    // 2) s = e^T v : per batch T x N, reduce K
    gemm_tn<64, 64, 4, 4, false><<<dim3(NN / 64, TT / 64, BB), 256>>>(
        e, pv, nullptr, ps, KK, TT, NN, NN, (long)KK * TT, (long)KK * NN,
        (long)TT * NN);

    // 3) alpha = softmax(gamma * s) over N (in place)
    softmax_k<<<BB * TT, 256>>>(ps, gp);

    // 4) c = v alpha^T : per batch K x T, reduce N
    gemm_nt_c<<<dim3(1, KK / 64, BB), 256>>>(pv, ps, pc);

    // 5) cos = (c^T e) / outer(|c|,|e|)
    finalize_k<<<BB, 256>>>(pc, e, out);
}